// round 15
// baseline (speedup 1.0000x reference)
#include <cuda_runtime.h>
#include <cstdint>
#include <math.h>

#define NBIN 65536
#define MAXB 16
#define NMAX 262144
#define ZN (MAXB * NBIN / 4)

#define SEL_TPB 1024
#define SEL_NCTA 296

#define GE_TPB 512
#define GE_NCTA 148
#define ROWB 1040                    // 260 words: conflict-free x LDS.128
#define XBUF (64 * ROWB)             // 66560
#define SLOT 112                     // 28 words: conflict-free fold STS.128
#define SW_OFF (2 * XBUF)            // 133120
#define SIDX_OFF (SW_OFF + 24576)    // 157696
#define SB_OFF (SIDX_OFF + 512)      // 158208
#define MBAR_OFF (SB_OFF + 96)       // 158304
#define SMEM_TOT (MBAR_OFF + 32)

// ---- device scratch (zero-init; every run restores zero state) ----
__device__ unsigned g_hist1[MAXB * NBIN];
__device__ unsigned g_hist2[MAXB * NBIN];
__device__ unsigned g_chunk1[MAXB * 256];
__device__ unsigned g_chunk2[MAXB * 256];
__device__ int g_list[NMAX];
__device__ int g_cnt;
__device__ unsigned g_bar[8];        // monotonic barrier counters (never reset)

__device__ __forceinline__ unsigned f2key(float s) {
    unsigned u = __float_as_uint(s);
    return (u & 0x80000000u) ? ~u : (u | 0x80000000u);
}
__device__ __forceinline__ unsigned long long ffma2(
    unsigned long long a, unsigned long long b, unsigned long long c) {
    unsigned long long d;
    asm("fma.rn.f32x2 %0, %1, %2, %3;" : "=l"(d) : "l"(a), "l"(b), "l"(c));
    return d;
}
__device__ __forceinline__ unsigned long long addf2(
    unsigned long long a, unsigned long long b) {
    unsigned long long d;
    asm("add.rn.f32x2 %0, %1, %2;" : "=l"(d) : "l"(a), "l"(b));
    return d;
}
__device__ __forceinline__ unsigned long long pack2(float x) {
    unsigned long long d;
    asm("mov.b64 %0, {%1, %1};" : "=l"(d) : "f"(x));
    return d;
}
__device__ __forceinline__ void unpack2(unsigned long long v, float& lo, float& hi) {
    asm("mov.b64 {%0, %1}, %2;" : "=f"(lo), "=f"(hi) : "l"(v));
}
__device__ __forceinline__ float getc(const float4& v, int s) {
    return (s == 0) ? v.x : (s == 1) ? v.y : (s == 2) ? v.z : v.w;
}
__device__ __forceinline__ uint32_t s2u(const void* p) {
    uint32_t a;
    asm("{ .reg .u64 t; cvta.to.shared.u64 t, %1; cvt.u32.u64 %0, t; }"
        : "=r"(a) : "l"(p));
    return a;
}
__device__ __forceinline__ void mbar_init(uint32_t mbar, uint32_t cnt) {
    asm volatile("mbarrier.init.shared.b64 [%0], %1;" :: "r"(mbar), "r"(cnt) : "memory");
}
__device__ __forceinline__ void mbar_expect(uint32_t mbar, uint32_t bytes) {
    asm volatile("mbarrier.arrive.expect_tx.shared.b64 _, [%0], %1;"
                 :: "r"(mbar), "r"(bytes) : "memory");
}
__device__ __forceinline__ void mbar_wait(uint32_t mbar, uint32_t parity) {
    asm volatile(
        "{\n\t.reg .pred P;\n"
        "WL_%=:\n\t"
        "mbarrier.try_wait.parity.acquire.cta.shared::cta.b64 P, [%0], %1, 0x989680;\n\t"
        "@P bra.uni WD_%=;\n\t"
        "bra.uni WL_%=;\n"
        "WD_%=:\n\t}"
        :: "r"(mbar), "r"(parity) : "memory");
}
__device__ __forceinline__ void bulk_copy(uint32_t dst, const void* src,
                                          uint32_t bytes, uint32_t mbar) {
    asm volatile(
        "cp.async.bulk.shared::cluster.global.mbarrier::complete_tx::bytes "
        "[%0], [%1], %2, [%3];"
        :: "r"(dst), "l"(src), "r"(bytes), "r"(mbar) : "memory");
}

// Reset-free grid barrier (SEL_NCTA CTAs, all co-resident).
__device__ __forceinline__ void gbar(int i) {
    __syncthreads();
    if (threadIdx.x == 0) {
        __threadfence();
        unsigned old = atomicAdd(&g_bar[i], 1u);
        unsigned target = old - (old % SEL_NCTA) + SEL_NCTA;
        unsigned cur;
        do {
            asm volatile("ld.acquire.gpu.global.u32 %0, [%1];"
                         : "=r"(cur) : "l"(&g_bar[i]) : "memory");
        } while ((int)(cur - target) < 0);
    }
    __syncthreads();
}

// Warp-collective: in a 256-entry array, find largest index idx such that the
// inclusive suffix sum at idx >= target, and rem = target - suffix(idx+1).
__device__ __forceinline__ void warp_select(const unsigned* __restrict__ a,
                                            unsigned target, int lane,
                                            int& idx, unsigned& rem) {
    unsigned T = 0;
    int bidx = -1;
    unsigned r = 0;
#pragma unroll
    for (int i = 7; i >= 0; i--) {
        unsigned v = a[i * 32 + lane];
        unsigned s = v;
#pragma unroll
        for (int off = 1; off < 32; off <<= 1) {
            unsigned n = __shfl_down_sync(0xffffffffu, s, off);
            if (lane + off < 32) s += n;
        }
        unsigned sn = __shfl_down_sync(0xffffffffu, s, 1);
        if (lane == 31) sn = 0;
        unsigned G = __shfl_sync(0xffffffffu, s, 0);
        bool found = (bidx < 0) && (T + s >= target) && (T + sn < target);
        unsigned m = __ballot_sync(0xffffffffu, found);
        if (m) {
            int src = __ffs((int)m) - 1;
            unsigned rv = target - (T + sn);
            rv = __shfl_sync(0xffffffffu, rv, src);
            if (bidx < 0) { bidx = i * 32 + src; r = rv; }
        }
        T += G;
    }
    idx = bidx;
    rem = r;
}

// Fused selection, 3 phases / 2 grid barriers. Per-batch scans are done
// warp-redundantly inside every CTA (warp w handles batch w), results in smem.
__global__ void __launch_bounds__(SEL_TPB, 2) sel_kernel(
    const float* __restrict__ scores,
    const int* __restrict__ bids,
    const float* __restrict__ b_cls,
    const int* __restrict__ nb_ptr,
    const int* __restrict__ k_ptr,
    float4* __restrict__ out4, int N) {
    __shared__ int sbucket1[MAXB];
    __shared__ unsigned srank1[MAXB];
    __shared__ unsigned skth[MAXB];
    __shared__ float sbq[24];
    __shared__ int warp_cnt[32];
    __shared__ int warp_off[32];
    __shared__ int cta_base;

    int t = threadIdx.x;
    int lane = t & 31, wid = t >> 5;
    int bid = blockIdx.x;
    int gid = bid * SEL_TPB + t;

    int B = nb_ptr ? *nb_ptr : 8;
    if (B < 1 || B > MAXB) B = 8;
    unsigned K = (unsigned)(k_ptr ? *k_ptr : 8192);

    // ---- P1: hist1 + chunk1; zero level-2 state; reset g_cnt ----
    if (gid == 0) g_cnt = 0;
    if (gid < ZN) reinterpret_cast<uint4*>(g_hist2)[gid] = make_uint4(0u, 0u, 0u, 0u);
    if (gid < MAXB * 256) g_chunk2[gid] = 0u;
    if (gid < N) {
        unsigned b = (unsigned)bids[gid];
        if (b < (unsigned)MAXB) {
            unsigned key = f2key(scores[gid]);
            atomicAdd(&g_hist1[b * NBIN + (key >> 16)], 1u);
            atomicAdd(&g_chunk1[b * 256 + (key >> 24)], 1u);
        }
    }
    gbar(0);

    // ---- P2: level-1 select (per-warp, in-CTA) then hist2 + chunk2 ----
    if (wid < B) {
        int cIdx, bIdx;
        unsigned remA, remB;
        warp_select(g_chunk1 + (size_t)wid * 256, K, lane, cIdx, remA);
        warp_select(g_hist1 + (size_t)wid * NBIN + cIdx * 256, remA, lane, bIdx, remB);
        if (lane == 0) {
            sbucket1[wid] = cIdx * 256 + bIdx;
            srank1[wid] = remB;
        }
    }
    __syncthreads();
    if (gid < N) {
        unsigned b = (unsigned)bids[gid];
        if (b < (unsigned)MAXB) {
            unsigned key = f2key(scores[gid]);
            if ((int)(key >> 16) == sbucket1[b]) {
                atomicAdd(&g_hist2[b * NBIN + (key & 0xFFFFu)], 1u);
                atomicAdd(&g_chunk2[b * 256 + ((key >> 8) & 0xFFu)], 1u);
            }
        }
    }
    gbar(1);

    // ---- P3: level-2 select -> kth key; zero level-1 state; compact+fill ----
    if (wid < B) {
        int c2, b2;
        unsigned remA2, remB2;
        warp_select(g_chunk2 + (size_t)wid * 256, srank1[wid], lane, c2, remA2);
        warp_select(g_hist2 + (size_t)wid * NBIN + c2 * 256, remA2, lane, b2, remB2);
        if (lane == 0)
            skth[wid] = ((unsigned)sbucket1[wid] << 16) | (unsigned)(c2 * 256 + b2);
    }
    if (t < 24) sbq[t] = (t < 6) ? 1.0f : b_cls[t - 6];
    __syncthreads();

    if (gid < ZN) reinterpret_cast<uint4*>(g_hist1)[gid] = make_uint4(0u, 0u, 0u, 0u);
    if (gid < MAXB * 256) g_chunk1[gid] = 0u;

    bool keep = false;
    if (gid < N) {
        unsigned b = (unsigned)bids[gid];
        unsigned key = f2key(scores[gid]);
        keep = (b < (unsigned)MAXB) && (key >= skth[b]);
        if (!keep) {
            float4* o = out4 + (size_t)gid * 6;
            o[0] = make_float4(1.f, 1.f, 1.f, 1.f);
            o[1] = make_float4(1.f, 1.f, sbq[6], sbq[7]);
            o[2] = make_float4(sbq[8], sbq[9], sbq[10], sbq[11]);
            o[3] = make_float4(sbq[12], sbq[13], sbq[14], sbq[15]);
            o[4] = make_float4(sbq[16], sbq[17], sbq[18], sbq[19]);
            o[5] = make_float4(sbq[20], sbq[21], sbq[22], sbq[23]);
        }
    }
    unsigned bal = __ballot_sync(0xffffffffu, keep);
    int nk = __popc(bal);
    if (lane == 0) warp_cnt[wid] = nk;
    __syncthreads();
    if (t < 32) {
        int v = warp_cnt[t];
        int inc = v;
#pragma unroll
        for (int o = 1; o < 32; o <<= 1) {
            int n = __shfl_up_sync(0xffffffffu, inc, o);
            if (t >= o) inc += n;
        }
        warp_off[t] = inc - v;
        if (t == 31) cta_base = atomicAdd(&g_cnt, inc);
    }
    __syncthreads();
    if (keep)
        g_list[cta_base + warp_off[wid] + __popc(bal & ((1u << lane) - 1u))] = gid;
}

// Staged GEMV (R11-proven): tile=64 pts, 512 thr = 8 k-slices x 2 out-halves,
// lane owns pts (l, l+32). Double-buffered cp.async.bulk; weight prefetch;
// coalesced jj-fastest epilogue.
__global__ void __launch_bounds__(GE_TPB, 1) gemv_kernel(
    const float* __restrict__ feats,
    const float* __restrict__ w_reg,
    const float* __restrict__ w_cls,
    const float* __restrict__ b_cls,
    const float* __restrict__ scale,
    float* __restrict__ out) {
    extern __shared__ char smem[];
    float* sw = (float*)(smem + SW_OFF);    // [256][24]
    int* sidx = (int*)(smem + SIDX_OFF);    // [2][64]
    float* sb = (float*)(smem + SB_OFF);
    uint32_t mb0 = s2u(smem + MBAR_OFF);
    uint32_t mb1 = mb0 + 8;

    int t = threadIdx.x;
    int l = t & 31, wid = t >> 5;
    int q = wid & 7;                 // k-slice [32q, 32q+32)
    int jh = wid >> 3;               // output half: floats [12jh, 12jh+12)

    if (t < 24) sb[t] = (t < 6) ? 1.0f : b_cls[t - 6];
    for (int i = t; i < 6144; i += GE_TPB) {
        int k = i / 24, j = i % 24;
        sw[i] = (j < 6) ? w_reg[k * 6 + j] : w_cls[k * 18 + (j - 6)];
    }
    if (t < 2) mbar_init(t == 0 ? mb0 : mb1, 1);
    float sc = scale[0];
    int T = g_cnt;
    int ntiles = (T + 63) >> 6;
    __syncthreads();

    int tile = blockIdx.x;
    int ph0 = 0, ph1 = 0;

    if (tile < ntiles) {
        int nv = min(64, T - (tile << 6));
        if (t < 64) sidx[t] = (t < nv) ? g_list[(tile << 6) + t] : 0;
        if (t == 0) mbar_expect(mb0, (unsigned)nv << 10);
    }
    __syncthreads();
    if (tile < ntiles && t < min(64, T - (tile << 6)))
        bulk_copy(s2u(smem) + t * ROWB, feats + (size_t)sidx[t] * 256, 1024, mb0);

    // per-(q,jh) weight base: k-stride = 96B = 6 ulonglong2
    const ulonglong2* wp = (const ulonglong2*)(sw + q * 768 + jh * 12);

    int b = 0;
    for (; tile < ntiles; tile += GE_NCTA, b ^= 1) {
        int nv = min(64, T - (tile << 6));
        int nxt = tile + GE_NCTA;
        int bn = b ^ 1;
        uint32_t mbn = bn ? mb1 : mb0;

        if (nxt < ntiles) {
            int nv2 = min(64, T - (nxt << 6));
            if (t < 64) sidx[bn * 64 + t] = (t < nv2) ? g_list[(nxt << 6) + t] : 0;
            if (t == 0) mbar_expect(mbn, (unsigned)nv2 << 10);
        }
        __syncthreads();
        if (nxt < ntiles) {
            int nv2 = min(64, T - (nxt << 6));
            if (t < nv2)
                bulk_copy(s2u(smem) + bn * XBUF + t * ROWB,
                          feats + (size_t)sidx[bn * 64 + t] * 256, 1024, mbn);
        }

        if (b == 0) { mbar_wait(mb0, ph0); ph0 ^= 1; }
        else        { mbar_wait(mb1, ph1); ph1 ^= 1; }

        // compute: pts (l, l+32), k in [32q,32q+32), output pairs [6jh,6jh+6)
        const float4* x0 = (const float4*)(smem + b * XBUF + l * ROWB) + q * 8;
        const float4* x1 = x0 + 32 * 65;   // +32 rows (65 float4 per row)
        unsigned long long acc0[6], acc1[6];
#pragma unroll
        for (int j = 0; j < 6; j++) { acc0[j] = 0ull; acc1[j] = 0ull; }

        ulonglong2 wA0 = wp[0], wA1 = wp[1], wA2 = wp[2];  // k = 32q
        float4 a0 = x0[0], a1 = x1[0];
#pragma unroll
        for (int c4 = 0; c4 < 8; c4++) {
            float4 n0, n1;
            if (c4 < 7) { n0 = x0[c4 + 1]; n1 = x1[c4 + 1]; }
#pragma unroll
            for (int s = 0; s < 4; s++) {
                ulonglong2 w0 = wA0, w1 = wA1, w2 = wA2;
                int kn = c4 * 4 + s + 1;
                if (kn < 32) {
                    const ulonglong2* wn = wp + kn * 6;
                    wA0 = wn[0]; wA1 = wn[1]; wA2 = wn[2];
                }
                unsigned long long xx0 = pack2(getc(a0, s));
                unsigned long long xx1 = pack2(getc(a1, s));
                acc0[0] = ffma2(xx0, w0.x, acc0[0]);
                acc0[1] = ffma2(xx0, w0.y, acc0[1]);
                acc0[2] = ffma2(xx0, w1.x, acc0[2]);
                acc0[3] = ffma2(xx0, w1.y, acc0[3]);
                acc0[4] = ffma2(xx0, w2.x, acc0[4]);
                acc0[5] = ffma2(xx0, w2.y, acc0[5]);
                acc1[0] = ffma2(xx1, w0.x, acc1[0]);
                acc1[1] = ffma2(xx1, w0.y, acc1[1]);
                acc1[2] = ffma2(xx1, w1.x, acc1[2]);
                acc1[3] = ffma2(xx1, w1.y, acc1[3]);
                acc1[4] = ffma2(xx1, w2.x, acc1[4]);
                acc1[5] = ffma2(xx1, w2.y, acc1[5]);
            }
            a0 = n0; a1 = n1;
        }
        __syncthreads();  // all x reads done; buffer b becomes scratch

        // single-phase fold store: slot (wid*32+l), 6 x STS.128
        // 512 slots x 112 B = 57344 <= XBUF; 28-word stride: conflict-free
        char* scratch = smem + b * XBUF;
        {
            ulonglong2* dst = (ulonglong2*)(scratch + (wid * 32 + l) * SLOT);
            dst[0] = make_ulonglong2(acc0[0], acc0[1]);
            dst[1] = make_ulonglong2(acc0[2], acc0[3]);
            dst[2] = make_ulonglong2(acc0[4], acc0[5]);
            dst[3] = make_ulonglong2(acc1[0], acc1[1]);
            dst[4] = make_ulonglong2(acc1[2], acc1[3]);
            dst[5] = make_ulonglong2(acc1[4], acc1[5]);
        }
        __syncthreads();

        // epilogue: fold 8 q-partials; jj fastest -> coalesced output rows
        for (int s = t; s < 768; s += GE_TPB) {
            int pt = s / 12, jj = s % 12;       // jj in [0,12)
            int jh2 = jj / 6, j6 = jj % 6;
            int pl = pt & 31, psub = pt >> 5;
            unsigned long long sum = 0ull;
#pragma unroll
            for (int q2 = 0; q2 < 8; q2++) {
                unsigned long long pv = *(const unsigned long long*)(
                    scratch + ((jh2 * 8 + q2) * 32 + pl) * SLOT + psub * 48 + j6 * 8);
                sum = addf2(sum, pv);
            }
            if (pt < nv) {
                float lo, hi;
                unpack2(sum, lo, hi);
                int col = jj << 1;
                float2 o;
                if (col < 6) { o.x = __expf(sc * lo); o.y = __expf(sc * hi); }
                else         { o.x = lo + sb[col];    o.y = hi + sb[col + 1]; }
                *(float2*)(out + (size_t)sidx[b * 64 + pt] * 24 + col) = o;
            }
        }
        __syncthreads();  // buffer b free for the next refill
    }
}

extern "C" void kernel_launch(void* const* d_in, const int* in_sizes, int n_in,
                              void* d_out, int out_size) {
    const float* feats  = (const float*)d_in[0];
    const float* scores = (const float*)d_in[1];
    const float* w_reg  = (const float*)d_in[2];
    const float* w_cls  = (const float*)d_in[3];
    const float* b_cls  = (const float*)d_in[4];
    const float* scale  = (const float*)d_in[5];
    const int*   bids   = (const int*)d_in[6];
    const int*   nb     = (n_in > 7) ? (const int*)d_in[7] : nullptr;
    const int*   kp     = (n_in > 8) ? (const int*)d_in[8] : nullptr;
    int N = in_sizes[0] / 256;

    static bool attr_set = false;
    if (!attr_set) {
        cudaFuncSetAttribute(gemv_kernel,
                             cudaFuncAttributeMaxDynamicSharedMemorySize, SMEM_TOT);
        attr_set = true;
    }

    sel_kernel<<<SEL_NCTA, SEL_TPB>>>(scores, bids, b_cls, nb, kp,
                                      (float4*)d_out, N);
    gemv_kernel<<<GE_NCTA, GE_TPB, SMEM_TOT>>>(feats, w_reg, w_cls, b_cls,
                                               scale, (float*)d_out);
}

// round 16
// speedup vs baseline: 1.1419x; 1.1419x over previous
#include <cuda_runtime.h>
#include <cstdint>
#include <math.h>

#define NBIN 65536
#define MAXB 16
#define NMAX 262144
#define ZN (MAXB * NBIN / 4)

#define SEL_TPB 1024
#define SEL_NCTA 296

#define GE_TPB 512
#define GE_NCTA 148
#define ROWB 1040                    // 260 words: conflict-free x LDS.128
#define XBUF (64 * ROWB)             // 66560
#define SLOT 112                     // 28 words: conflict-free fold STS.128
#define SW_OFF (2 * XBUF)            // 133120
#define SIDX_OFF (SW_OFF + 24576)    // 157696
#define SB_OFF (SIDX_OFF + 512)      // 158208
#define MBAR_OFF (SB_OFF + 96)       // 158304
#define SMEM_TOT (MBAR_OFF + 32)

// ---- device scratch (zero-init; every run restores zero state) ----
__device__ unsigned g_hist1[MAXB * NBIN];
__device__ unsigned g_chunk1[MAXB * 256];
__device__ unsigned g_bucket1[MAXB];
__device__ unsigned g_rank1[MAXB];
__device__ int g_ccnt[MAXB];
__device__ unsigned g_cand_key[MAXB * NMAX];
__device__ int g_cand_gid[MAXB * NMAX];
__device__ int g_list[NMAX];
__device__ int g_cnt;
__device__ unsigned g_bar[8];        // monotonic barrier counters (never reset)

__device__ __forceinline__ unsigned f2key(float s) {
    unsigned u = __float_as_uint(s);
    return (u & 0x80000000u) ? ~u : (u | 0x80000000u);
}
__device__ __forceinline__ unsigned long long ffma2(
    unsigned long long a, unsigned long long b, unsigned long long c) {
    unsigned long long d;
    asm("fma.rn.f32x2 %0, %1, %2, %3;" : "=l"(d) : "l"(a), "l"(b), "l"(c));
    return d;
}
__device__ __forceinline__ unsigned long long addf2(
    unsigned long long a, unsigned long long b) {
    unsigned long long d;
    asm("add.rn.f32x2 %0, %1, %2;" : "=l"(d) : "l"(a), "l"(b));
    return d;
}
__device__ __forceinline__ unsigned long long pack2(float x) {
    unsigned long long d;
    asm("mov.b64 %0, {%1, %1};" : "=l"(d) : "f"(x));
    return d;
}
__device__ __forceinline__ void unpack2(unsigned long long v, float& lo, float& hi) {
    asm("mov.b64 {%0, %1}, %2;" : "=f"(lo), "=f"(hi) : "l"(v));
}
__device__ __forceinline__ float getc(const float4& v, int s) {
    return (s == 0) ? v.x : (s == 1) ? v.y : (s == 2) ? v.z : v.w;
}
__device__ __forceinline__ uint32_t s2u(const void* p) {
    uint32_t a;
    asm("{ .reg .u64 t; cvta.to.shared.u64 t, %1; cvt.u32.u64 %0, t; }"
        : "=r"(a) : "l"(p));
    return a;
}
__device__ __forceinline__ void mbar_init(uint32_t mbar, uint32_t cnt) {
    asm volatile("mbarrier.init.shared.b64 [%0], %1;" :: "r"(mbar), "r"(cnt) : "memory");
}
__device__ __forceinline__ void mbar_expect(uint32_t mbar, uint32_t bytes) {
    asm volatile("mbarrier.arrive.expect_tx.shared.b64 _, [%0], %1;"
                 :: "r"(mbar), "r"(bytes) : "memory");
}
__device__ __forceinline__ void mbar_wait(uint32_t mbar, uint32_t parity) {
    asm volatile(
        "{\n\t.reg .pred P;\n"
        "WL_%=:\n\t"
        "mbarrier.try_wait.parity.acquire.cta.shared::cta.b64 P, [%0], %1, 0x989680;\n\t"
        "@P bra.uni WD_%=;\n\t"
        "bra.uni WL_%=;\n"
        "WD_%=:\n\t}"
        :: "r"(mbar), "r"(parity) : "memory");
}
__device__ __forceinline__ void bulk_copy(uint32_t dst, const void* src,
                                          uint32_t bytes, uint32_t mbar) {
    asm volatile(
        "cp.async.bulk.shared::cluster.global.mbarrier::complete_tx::bytes "
        "[%0], [%1], %2, [%3];"
        :: "r"(dst), "l"(src), "r"(bytes), "r"(mbar) : "memory");
}

// Reset-free grid barrier (SEL_NCTA CTAs, all co-resident).
__device__ __forceinline__ void gbar(int i) {
    __syncthreads();
    if (threadIdx.x == 0) {
        __threadfence();
        unsigned old = atomicAdd(&g_bar[i], 1u);
        unsigned target = old - (old % SEL_NCTA) + SEL_NCTA;
        unsigned cur;
        do {
            asm volatile("ld.acquire.gpu.global.u32 %0, [%1];"
                         : "=r"(cur) : "l"(&g_bar[i]) : "memory");
        } while ((int)(cur - target) < 0);
    }
    __syncthreads();
}

// Warp-collective select over a 256-entry array (generic pointer: works for
// smem too): largest idx with suffix(idx) >= target; rem = target-suffix(idx+1).
__device__ __forceinline__ void warp_select(const unsigned* __restrict__ a,
                                            unsigned target, int lane,
                                            int& idx, unsigned& rem) {
    unsigned T = 0;
    int bidx = -1;
    unsigned r = 0;
#pragma unroll
    for (int i = 7; i >= 0; i--) {
        unsigned v = a[i * 32 + lane];
        unsigned s = v;
#pragma unroll
        for (int off = 1; off < 32; off <<= 1) {
            unsigned n = __shfl_down_sync(0xffffffffu, s, off);
            if (lane + off < 32) s += n;
        }
        unsigned sn = __shfl_down_sync(0xffffffffu, s, 1);
        if (lane == 31) sn = 0;
        unsigned G = __shfl_sync(0xffffffffu, s, 0);
        bool found = (bidx < 0) && (T + s >= target) && (T + sn < target);
        unsigned m = __ballot_sync(0xffffffffu, found);
        if (m) {
            int src = __ffs((int)m) - 1;
            unsigned rv = target - (T + sn);
            rv = __shfl_sync(0xffffffffu, rv, src);
            if (bidx < 0) { bidx = i * 32 + src; r = rv; }
        }
        T += G;
    }
    idx = bidx;
    rem = r;
}

// CTA b handles batch b; threads 0..255 active; two shfl suffix scans.
__device__ void scan_phase(int b, unsigned target,
                           unsigned* wsum, int* s_sel, unsigned* s_rem) {
    const unsigned* h  = g_hist1  + (size_t)b * NBIN;
    const unsigned* ch = g_chunk1 + (size_t)b * 256;

    int t = threadIdx.x, lane = t & 31, w = t >> 5;
    unsigned v = 0, x = 0;

    if (t < 256) {
        v = ch[t];
        x = v;
#pragma unroll
        for (int off = 1; off < 32; off <<= 1) {
            unsigned nv = __shfl_down_sync(0xffffffffu, x, off);
            if (lane + off < 32) x += nv;
        }
        if (lane == 0) wsum[w] = x;
    }
    __syncthreads();
    if (t < 256) {
        unsigned add = 0;
        for (int w2 = w + 1; w2 < 8; w2++) add += wsum[w2];
        unsigned s = x + add;
        if (s >= target && s - v < target) { *s_sel = t; *s_rem = target - (s - v); }
    }
    __syncthreads();
    int sel = *s_sel;
    unsigned rem = *s_rem;
    __syncthreads();

    if (t < 256) {
        v = h[sel * 256 + t];
        x = v;
#pragma unroll
        for (int off = 1; off < 32; off <<= 1) {
            unsigned nv = __shfl_down_sync(0xffffffffu, x, off);
            if (lane + off < 32) x += nv;
        }
        if (lane == 0) wsum[w] = x;
    }
    __syncthreads();
    if (t < 256) {
        unsigned add = 0;
        for (int w2 = w + 1; w2 < 8; w2++) add += wsum[w2];
        unsigned s = x + add;
        if (s >= rem && s - v < rem) {
            g_bucket1[b] = (unsigned)(sel * 256 + t);
            g_rank1[b] = rem - (s - v);
        }
    }
}

// Fused selection, candidate-based: hist1 -> scan1 -> classify/compact/fill
// (one N-pass; ambiguous bucket points go to tiny per-batch candidate buffers)
// -> per-batch candidate resolution. 3 grid barriers, no level-2 histogram.
__global__ void __launch_bounds__(SEL_TPB, 2) sel_kernel(
    const float* __restrict__ scores,
    const int* __restrict__ bids,
    const float* __restrict__ b_cls,
    const int* __restrict__ nb_ptr,
    const int* __restrict__ k_ptr,
    float4* __restrict__ out4, int N) {
    __shared__ unsigned wsum[8];
    __shared__ int s_sel;
    __shared__ unsigned s_rem;
    __shared__ float sbq[24];
    __shared__ int warp_cnt[32];
    __shared__ int warp_off[32];
    __shared__ int cta_base;
    __shared__ unsigned h8[256];
    __shared__ int s_selA;
    __shared__ unsigned s_remA;
    __shared__ unsigned s_kth;

    int t = threadIdx.x;
    int lane = t & 31, wid = t >> 5;
    int bid = blockIdx.x;
    int gid = bid * SEL_TPB + t;

    int B = nb_ptr ? *nb_ptr : 8;
    if (B < 1 || B > MAXB) B = 8;
    unsigned K = (unsigned)(k_ptr ? *k_ptr : 8192);

    if (t < 24) sbq[t] = (t < 6) ? 1.0f : b_cls[t - 6];

    // ---- P1: hist1 + chunk1; reset counters ----
    if (gid == 0) g_cnt = 0;
    if (gid < MAXB) g_ccnt[gid] = 0;
    if (gid < N) {
        unsigned b = (unsigned)bids[gid];
        if (b < (unsigned)MAXB) {
            unsigned key = f2key(scores[gid]);
            atomicAdd(&g_hist1[b * NBIN + (key >> 16)], 1u);
            atomicAdd(&g_chunk1[b * 256 + (key >> 24)], 1u);
        }
    }
    gbar(0);

    // ---- P2: scan level 1 (CTA b handles batch b) ----
    if (bid < B) scan_phase(bid, K, wsum, &s_sel, &s_rem);
    gbar(1);

    // ---- P3: single classify pass + zero level-1 state ----
    if (gid < ZN) reinterpret_cast<uint4*>(g_hist1)[gid] = make_uint4(0u, 0u, 0u, 0u);
    if (gid < MAXB * 256) g_chunk1[gid] = 0u;

    bool keep = false;
    {
        bool cand = false;
        unsigned key = 0, b = 0;
        if (gid < N) {
            b = (unsigned)bids[gid];
            if (b < (unsigned)MAXB) {
                key = f2key(scores[gid]);
                unsigned bk = g_bucket1[b];
                unsigned hi16 = key >> 16;
                if (hi16 > bk) keep = true;
                else if (hi16 == bk) cand = true;
                else {
                    float4* o = out4 + (size_t)gid * 6;
                    o[0] = make_float4(1.f, 1.f, 1.f, 1.f);
                    o[1] = make_float4(1.f, 1.f, sbq[6], sbq[7]);
                    o[2] = make_float4(sbq[8], sbq[9], sbq[10], sbq[11]);
                    o[3] = make_float4(sbq[12], sbq[13], sbq[14], sbq[15]);
                    o[4] = make_float4(sbq[16], sbq[17], sbq[18], sbq[19]);
                    o[5] = make_float4(sbq[20], sbq[21], sbq[22], sbq[23]);
                }
            }
        }
        if (cand) {
            int pos = atomicAdd(&g_ccnt[b], 1);
            g_cand_key[(size_t)b * NMAX + pos] = key;
            g_cand_gid[(size_t)b * NMAX + pos] = gid;
        }
    }
    // CTA-aggregated append of definite keeps
    unsigned bal = __ballot_sync(0xffffffffu, keep);
    int nk = __popc(bal);
    if (lane == 0) warp_cnt[wid] = nk;
    __syncthreads();
    if (t < 32) {
        int v = warp_cnt[t];
        int inc = v;
#pragma unroll
        for (int o = 1; o < 32; o <<= 1) {
            int n = __shfl_up_sync(0xffffffffu, inc, o);
            if (t >= o) inc += n;
        }
        warp_off[t] = inc - v;
        if (t == 31) cta_base = atomicAdd(&g_cnt, inc);
    }
    __syncthreads();
    if (keep)
        g_list[cta_base + warp_off[wid] + __popc(bal & ((1u << lane) - 1u))] = gid;
    gbar(2);

    // ---- P4: candidate resolution, CTA b handles batch b ----
    if (bid >= B) return;
    int cnt = g_ccnt[bid];
    unsigned r = g_rank1[bid];
    const unsigned* ck = g_cand_key + (size_t)bid * NMAX;
    const int* cg = g_cand_gid + (size_t)bid * NMAX;

    if (t < 256) h8[t] = 0u;
    __syncthreads();
    for (int i = t; i < cnt; i += SEL_TPB)
        atomicAdd(&h8[(ck[i] >> 8) & 0xFFu], 1u);
    __syncthreads();
    if (wid == 0) {
        int selA; unsigned remA;
        warp_select(h8, r, lane, selA, remA);
        if (lane == 0) { s_selA = selA; s_remA = remA; }
    }
    __syncthreads();
    int selA = s_selA;
    unsigned remA = s_remA;
    __syncthreads();
    if (t < 256) h8[t] = 0u;
    __syncthreads();
    for (int i = t; i < cnt; i += SEL_TPB) {
        unsigned key = ck[i];
        if (((key >> 8) & 0xFFu) == (unsigned)selA)
            atomicAdd(&h8[key & 0xFFu], 1u);
    }
    __syncthreads();
    if (wid == 0) {
        int selB; unsigned remB;
        warp_select(h8, remA, lane, selB, remB);
        if (lane == 0)
            s_kth = (g_bucket1[bid] << 16) | ((unsigned)selA << 8) | (unsigned)selB;
    }
    __syncthreads();
    unsigned kth = s_kth;

    // compact kept candidates / fill pruned candidates
    for (int i0 = 0; i0 < cnt; i0 += SEL_TPB) {
        int i = i0 + t;
        bool kp = false;
        unsigned key = 0; int g2 = 0;
        if (i < cnt) {
            key = ck[i];
            g2 = cg[i];
            kp = key >= kth;
            if (!kp) {
                float4* o = out4 + (size_t)g2 * 6;
                o[0] = make_float4(1.f, 1.f, 1.f, 1.f);
                o[1] = make_float4(1.f, 1.f, sbq[6], sbq[7]);
                o[2] = make_float4(sbq[8], sbq[9], sbq[10], sbq[11]);
                o[3] = make_float4(sbq[12], sbq[13], sbq[14], sbq[15]);
                o[4] = make_float4(sbq[16], sbq[17], sbq[18], sbq[19]);
                o[5] = make_float4(sbq[20], sbq[21], sbq[22], sbq[23]);
            }
        }
        unsigned b2 = __ballot_sync(0xffffffffu, kp);
        int n2 = __popc(b2);
        if (n2) {
            int gb = 0;
            if (lane == 0) gb = atomicAdd(&g_cnt, n2);
            gb = __shfl_sync(0xffffffffu, gb, 0);
            if (kp) g_list[gb + __popc(b2 & ((1u << lane) - 1u))] = g2;
        }
    }
}

// Staged GEMV (R11-proven, 38.4us): tile=64 pts, 512 thr = 8 k-slices x 2
// output-halves, lane owns pts (l, l+32). Double-buffered cp.async.bulk;
// weight prefetch one k ahead.
__global__ void __launch_bounds__(GE_TPB, 1) gemv_kernel(
    const float* __restrict__ feats,
    const float* __restrict__ w_reg,
    const float* __restrict__ w_cls,
    const float* __restrict__ b_cls,
    const float* __restrict__ scale,
    float* __restrict__ out) {
    extern __shared__ char smem[];
    float* sw = (float*)(smem + SW_OFF);    // [256][24]
    int* sidx = (int*)(smem + SIDX_OFF);    // [2][64]
    float* sb = (float*)(smem + SB_OFF);
    uint32_t mb0 = s2u(smem + MBAR_OFF);
    uint32_t mb1 = mb0 + 8;

    int t = threadIdx.x;
    int l = t & 31, wid = t >> 5;
    int q = wid & 7;                 // k-slice [32q, 32q+32)
    int jh = wid >> 3;               // output half: floats [12jh, 12jh+12)

    if (t < 24) sb[t] = (t < 6) ? 1.0f : b_cls[t - 6];
    for (int i = t; i < 6144; i += GE_TPB) {
        int k = i / 24, j = i % 24;
        sw[i] = (j < 6) ? w_reg[k * 6 + j] : w_cls[k * 18 + (j - 6)];
    }
    if (t < 2) mbar_init(t == 0 ? mb0 : mb1, 1);
    float sc = scale[0];
    int T = g_cnt;
    int ntiles = (T + 63) >> 6;
    __syncthreads();

    int tile = blockIdx.x;
    int ph0 = 0, ph1 = 0;

    if (tile < ntiles) {
        int nv = min(64, T - (tile << 6));
        if (t < 64) sidx[t] = (t < nv) ? g_list[(tile << 6) + t] : 0;
        if (t == 0) mbar_expect(mb0, (unsigned)nv << 10);
    }
    __syncthreads();
    if (tile < ntiles && t < min(64, T - (tile << 6)))
        bulk_copy(s2u(smem) + t * ROWB, feats + (size_t)sidx[t] * 256, 1024, mb0);

    // per-(q,jh) weight base: k-stride = 96B = 6 ulonglong2
    const ulonglong2* wp = (const ulonglong2*)(sw + q * 768 + jh * 12);

    int b = 0;
    for (; tile < ntiles; tile += GE_NCTA, b ^= 1) {
        int nv = min(64, T - (tile << 6));
        int nxt = tile + GE_NCTA;
        int bn = b ^ 1;
        uint32_t mbn = bn ? mb1 : mb0;

        if (nxt < ntiles) {
            int nv2 = min(64, T - (nxt << 6));
            if (t < 64) sidx[bn * 64 + t] = (t < nv2) ? g_list[(nxt << 6) + t] : 0;
            if (t == 0) mbar_expect(mbn, (unsigned)nv2 << 10);
        }
        __syncthreads();
        if (nxt < ntiles) {
            int nv2 = min(64, T - (nxt << 6));
            if (t < nv2)
                bulk_copy(s2u(smem) + bn * XBUF + t * ROWB,
                          feats + (size_t)sidx[bn * 64 + t] * 256, 1024, mbn);
        }

        if (b == 0) { mbar_wait(mb0, ph0); ph0 ^= 1; }
        else        { mbar_wait(mb1, ph1); ph1 ^= 1; }

        // compute: pts (l, l+32), k in [32q,32q+32), output pairs [6jh,6jh+6)
        const float4* x0 = (const float4*)(smem + b * XBUF + l * ROWB) + q * 8;
        const float4* x1 = x0 + 32 * 65;   // +32 rows (65 float4 per row)
        unsigned long long acc0[6], acc1[6];
#pragma unroll
        for (int j = 0; j < 6; j++) { acc0[j] = 0ull; acc1[j] = 0ull; }

        ulonglong2 wA0 = wp[0], wA1 = wp[1], wA2 = wp[2];  // k = 32q
        float4 a0 = x0[0], a1 = x1[0];
#pragma unroll
        for (int c4 = 0; c4 < 8; c4++) {
            float4 n0, n1;
            if (c4 < 7) { n0 = x0[c4 + 1]; n1 = x1[c4 + 1]; }
#pragma unroll
            for (int s = 0; s < 4; s++) {
                ulonglong2 w0 = wA0, w1 = wA1, w2 = wA2;
                int kn = c4 * 4 + s + 1;
                if (kn < 32) {
                    const ulonglong2* wn = wp + kn * 6;
                    wA0 = wn[0]; wA1 = wn[1]; wA2 = wn[2];
                }
                unsigned long long xx0 = pack2(getc(a0, s));
                unsigned long long xx1 = pack2(getc(a1, s));
                acc0[0] = ffma2(xx0, w0.x, acc0[0]);
                acc0[1] = ffma2(xx0, w0.y, acc0[1]);
                acc0[2] = ffma2(xx0, w1.x, acc0[2]);
                acc0[3] = ffma2(xx0, w1.y, acc0[3]);
                acc0[4] = ffma2(xx0, w2.x, acc0[4]);
                acc0[5] = ffma2(xx0, w2.y, acc0[5]);
                acc1[0] = ffma2(xx1, w0.x, acc1[0]);
                acc1[1] = ffma2(xx1, w0.y, acc1[1]);
                acc1[2] = ffma2(xx1, w1.x, acc1[2]);
                acc1[3] = ffma2(xx1, w1.y, acc1[3]);
                acc1[4] = ffma2(xx1, w2.x, acc1[4]);
                acc1[5] = ffma2(xx1, w2.y, acc1[5]);
            }
            a0 = n0; a1 = n1;
        }
        __syncthreads();  // all x reads done; buffer b becomes scratch

        // single-phase fold store: slot (wid*32+l), 6 x STS.128
        // 512 slots x 112 B = 57344 <= XBUF; 28-word stride: conflict-free
        char* scratch = smem + b * XBUF;
        {
            ulonglong2* dst = (ulonglong2*)(scratch + (wid * 32 + l) * SLOT);
            dst[0] = make_ulonglong2(acc0[0], acc0[1]);
            dst[1] = make_ulonglong2(acc0[2], acc0[3]);
            dst[2] = make_ulonglong2(acc0[4], acc0[5]);
            dst[3] = make_ulonglong2(acc1[0], acc1[1]);
            dst[4] = make_ulonglong2(acc1[2], acc1[3]);
            dst[5] = make_ulonglong2(acc1[4], acc1[5]);
        }
        __syncthreads();

        // epilogue: fold 8 q-partials per (point, output-pair)
        for (int s = t; s < 768; s += GE_TPB) {
            int pt = s & 63, jj = s >> 6;       // jj in [0,12)
            int jh2 = jj / 6, j6 = jj % 6;
            int pl = pt & 31, psub = pt >> 5;
            unsigned long long sum = 0ull;
#pragma unroll
            for (int q2 = 0; q2 < 8; q2++) {
                unsigned long long pv = *(const unsigned long long*)(
                    scratch + ((jh2 * 8 + q2) * 32 + pl) * SLOT + psub * 48 + j6 * 8);
                sum = addf2(sum, pv);
            }
            if (pt < nv) {
                float lo, hi;
                unpack2(sum, lo, hi);
                int col = jj << 1;
                float2 o;
                if (col < 6) { o.x = __expf(sc * lo); o.y = __expf(sc * hi); }
                else         { o.x = lo + sb[col];    o.y = hi + sb[col + 1]; }
                *(float2*)(out + (size_t)sidx[b * 64 + pt] * 24 + col) = o;
            }
        }
        __syncthreads();  // buffer b free for the next refill
    }
}

extern "C" void kernel_launch(void* const* d_in, const int* in_sizes, int n_in,
                              void* d_out, int out_size) {
    const float* feats  = (const float*)d_in[0];
    const float* scores = (const float*)d_in[1];
    const float* w_reg  = (const float*)d_in[2];
    const float* w_cls  = (const float*)d_in[3];
    const float* b_cls  = (const float*)d_in[4];
    const float* scale  = (const float*)d_in[5];
    const int*   bids   = (const int*)d_in[6];
    const int*   nb     = (n_in > 7) ? (const int*)d_in[7] : nullptr;
    const int*   kp     = (n_in > 8) ? (const int*)d_in[8] : nullptr;
    int N = in_sizes[0] / 256;

    static bool attr_set = false;
    if (!attr_set) {
        cudaFuncSetAttribute(gemv_kernel,
                             cudaFuncAttributeMaxDynamicSharedMemorySize, SMEM_TOT);
        attr_set = true;
    }

    sel_kernel<<<SEL_NCTA, SEL_TPB>>>(scores, bids, b_cls, nb, kp,
                                      (float4*)d_out, N);
    gemv_kernel<<<GE_NCTA, GE_TPB, SMEM_TOT>>>(feats, w_reg, w_cls, b_cls,
                                               scale, (float*)d_out);
}